// round 4
// baseline (speedup 1.0000x reference)
#include <cuda_runtime.h>
#include <cuda_fp16.h>
#include <cstdint>

#define T_TOK 4096
#define H_DIM 1024
#define F_DIM 2816
#define N_EXP 8
#define TOTAL_ROWS (2*T_TOK)
#define W_PER ((size_t)H_DIM * F_DIM)
#define W_ELEMS (8ull*1024ull*2816ull)

#define BM 128
#define BN 128
#define BKK 32
#define AST 40      // A smem row stride (halves)
#define BST 136     // B smem row stride (halves)
#define NSTAGE 4
#define A_SH (BM * AST)                 // 5120 halves
#define B_SH (BKK * BST)                // 4352 halves

// ---------------- device scratch ---------------------------------------------
__device__ __half g_wg16[W_ELEMS];      // [E][H][F]
__device__ __half g_wu16[W_ELEMS];      // [E][H][F]
__device__ __half g_wd16[W_ELEMS];      // [E][F][H]
__device__ __half g_x16[(size_t)T_TOK * H_DIM];
__device__ __half g_hbuf[(size_t)TOTAL_ROWS * F_DIM];
__device__ int    g_counts[N_EXP];
__device__ int    g_cursor[N_EXP];
__device__ int    g_offs[N_EXP];
__device__ int    g_eid[TOTAL_ROWS];
__device__ float  g_ewt[TOTAL_ROWS];
__device__ int    g_rows[TOTAL_ROWS];
__device__ float  g_wv[TOTAL_ROWS];
__device__ int    g_tile_e[80];
__device__ int    g_tile_r0[80];
__device__ int    g_tile_rows[80];
__device__ int    g_tile_count;

// ---------------- PTX helpers -------------------------------------------------
__device__ __forceinline__ unsigned smem_u32(const void* p) {
    return (unsigned)__cvta_generic_to_shared(p);
}
__device__ __forceinline__ void cp_async16(const void* smem, const void* g) {
    asm volatile("cp.async.cg.shared.global [%0], [%1], 16;"
                 :: "r"(smem_u32(smem)), "l"(g));
}
__device__ __forceinline__ void cp_commit() {
    asm volatile("cp.async.commit_group;" ::: "memory");
}
template <int N>
__device__ __forceinline__ void cp_wait() {
    asm volatile("cp.async.wait_group %0;" :: "n"(N) : "memory");
}
__device__ __forceinline__ void ldsm_x4(uint32_t r[4], const __half* p) {
    asm volatile("ldmatrix.sync.aligned.m8n8.x4.shared.b16 {%0,%1,%2,%3}, [%4];"
                 : "=r"(r[0]), "=r"(r[1]), "=r"(r[2]), "=r"(r[3])
                 : "r"(smem_u32(p)));
}
__device__ __forceinline__ void ldsm_x4_t(uint32_t r[4], const __half* p) {
    asm volatile("ldmatrix.sync.aligned.m8n8.x4.trans.shared.b16 {%0,%1,%2,%3}, [%4];"
                 : "=r"(r[0]), "=r"(r[1]), "=r"(r[2]), "=r"(r[3])
                 : "r"(smem_u32(p)));
}
__device__ __forceinline__ void mma_16816(float* c, const uint32_t* a,
                                          uint32_t b0, uint32_t b1) {
    asm volatile(
        "mma.sync.aligned.m16n8k16.row.col.f32.f16.f16.f32 "
        "{%0,%1,%2,%3},{%4,%5,%6,%7},{%8,%9},{%0,%1,%2,%3};"
        : "+f"(c[0]), "+f"(c[1]), "+f"(c[2]), "+f"(c[3])
        : "r"(a[0]), "r"(a[1]), "r"(a[2]), "r"(a[3]), "r"(b0), "r"(b1));
}

// ---------------- tiny kernels ----------------------------------------------
__global__ void init_kernel() {
    int i = threadIdx.x;
    if (i < N_EXP) { g_counts[i] = 0; g_cursor[i] = 0; }
}

__global__ void zero_out_kernel(float4* out) {
    size_t n = (size_t)T_TOK * H_DIM / 4;
    for (size_t i = blockIdx.x * (size_t)blockDim.x + threadIdx.x; i < n;
         i += (size_t)gridDim.x * blockDim.x)
        out[i] = make_float4(0.f, 0.f, 0.f, 0.f);
}

__global__ void convert_kernel(const float4* __restrict__ wg,
                               const float4* __restrict__ wu,
                               const float4* __restrict__ wd) {
    size_t n = W_ELEMS / 4;
    __half2* og = (__half2*)g_wg16;
    __half2* ou = (__half2*)g_wu16;
    __half2* od = (__half2*)g_wd16;
    for (size_t i = blockIdx.x * (size_t)blockDim.x + threadIdx.x; i < n;
         i += (size_t)gridDim.x * blockDim.x) {
        float4 a = wg[i];
        og[2*i]   = __floats2half2_rn(a.x, a.y);
        og[2*i+1] = __floats2half2_rn(a.z, a.w);
        float4 b = wu[i];
        ou[2*i]   = __floats2half2_rn(b.x, b.y);
        ou[2*i+1] = __floats2half2_rn(b.z, b.w);
        float4 c = wd[i];
        od[2*i]   = __floats2half2_rn(c.x, c.y);
        od[2*i+1] = __floats2half2_rn(c.z, c.w);
    }
}

// ---------------- RMSNorm + router + top2 ------------------------------------
__global__ void rmsnorm_router_kernel(const float* __restrict__ hs,
                                      const float* __restrict__ lnw,
                                      const float* __restrict__ rw) {
    const int t = blockIdx.x;
    const int tid = threadIdx.x, lane = tid & 31, warp = tid >> 5;

    float4 xv = *(const float4*)(hs + (size_t)t * H_DIM + tid * 4);
    float ss = xv.x*xv.x + xv.y*xv.y + xv.z*xv.z + xv.w*xv.w;
    #pragma unroll
    for (int o = 16; o; o >>= 1) ss += __shfl_xor_sync(0xffffffffu, ss, o);

    __shared__ float sred[8];
    __shared__ float sinv;
    if (lane == 0) sred[warp] = ss;
    __syncthreads();
    if (tid == 0) {
        float v = 0.f;
        #pragma unroll
        for (int w = 0; w < 8; w++) v += sred[w];
        sinv = rsqrtf(v * (1.0f / H_DIM) + 1e-5f);
    }
    __syncthreads();
    float inv = sinv;

    float4 lw = *(const float4*)(lnw + tid * 4);
    float xn[4] = {xv.x*inv*lw.x, xv.y*inv*lw.y, xv.z*inv*lw.z, xv.w*inv*lw.w};

    __half2* xd = (__half2*)(g_x16 + (size_t)t * H_DIM + tid * 4);
    xd[0] = __floats2half2_rn(xn[0], xn[1]);
    xd[1] = __floats2half2_rn(xn[2], xn[3]);

    float lp[8] = {0,0,0,0,0,0,0,0};
    #pragma unroll
    for (int r = 0; r < 4; r++) {
        const float4 w0 = *(const float4*)(rw + (size_t)(tid*4 + r) * N_EXP);
        const float4 w1 = *(const float4*)(rw + (size_t)(tid*4 + r) * N_EXP + 4);
        float xr = xn[r];
        lp[0] += xr*w0.x; lp[1] += xr*w0.y; lp[2] += xr*w0.z; lp[3] += xr*w0.w;
        lp[4] += xr*w1.x; lp[5] += xr*w1.y; lp[6] += xr*w1.z; lp[7] += xr*w1.w;
    }
    #pragma unroll
    for (int e = 0; e < 8; e++)
        #pragma unroll
        for (int o = 16; o; o >>= 1) lp[e] += __shfl_xor_sync(0xffffffffu, lp[e], o);

    __shared__ float sl[8][8];
    if (lane == 0) {
        #pragma unroll
        for (int e = 0; e < 8; e++) sl[warp][e] = lp[e];
    }
    __syncthreads();
    if (tid == 0) {
        float l[8], m = -1e30f;
        #pragma unroll
        for (int e = 0; e < 8; e++) {
            float v = 0.f;
            #pragma unroll
            for (int w = 0; w < 8; w++) v += sl[w][e];
            l[e] = v; m = fmaxf(m, v);
        }
        float p[8], s = 0.f;
        #pragma unroll
        for (int e = 0; e < 8; e++) { p[e] = expf(l[e] - m); s += p[e]; }
        float is = 1.f / s;
        int b1 = 0; float v1 = -1.f;
        #pragma unroll
        for (int e = 0; e < 8; e++) if (p[e] > v1) { v1 = p[e]; b1 = e; }
        int b2 = 0; float v2 = -1.f;
        #pragma unroll
        for (int e = 0; e < 8; e++) if (e != b1 && p[e] > v2) { v2 = p[e]; b2 = e; }
        g_eid[2*t]   = b1; g_ewt[2*t]   = v1 * is;
        g_eid[2*t+1] = b2; g_ewt[2*t+1] = v2 * is;
        atomicAdd(&g_counts[b1], 1);
        atomicAdd(&g_counts[b2], 1);
    }
}

__global__ void build_tiles_kernel() {
    int off = 0;
    for (int e = 0; e < N_EXP; e++) { g_offs[e] = off; off += g_counts[e]; }
    int tc = 0;
    for (int e = 0; e < N_EXP; e++) {
        int beg = g_offs[e], end = beg + g_counts[e];
        for (int r = beg; r < end; r += 128) {
            g_tile_e[tc] = e; g_tile_r0[tc] = r;
            g_tile_rows[tc] = min(128, end - r);
            tc++;
        }
    }
    g_tile_count = tc;
}

__global__ void scatter_kernel() {
    int i = blockIdx.x * blockDim.x + threadIdx.x;
    if (i < TOTAL_ROWS) {
        int e = g_eid[i];
        int pos = g_offs[e] + atomicAdd(&g_cursor[e], 1);
        g_rows[pos] = i >> 1;
        g_wv[pos] = g_ewt[i];
    }
}

// ---------------- fused gate+up+SwiGLU GEMM ----------------------------------
// C = [gate | up] for one 128-row tile x 128 F-cols; epilogue writes hbuf fp16.
__global__ void __launch_bounds__(256, 1) gateup_kernel() {
    const int mt = blockIdx.y;
    if (mt >= g_tile_count) return;
    const int e    = g_tile_e[mt];
    const int r0   = g_tile_r0[mt];
    const int rows = g_tile_rows[mt];
    const int n0   = blockIdx.x * BN;
    constexpr int KI = H_DIM / BKK;          // 32

    extern __shared__ __half sm[];
    // stage s: A at s*STG, Bg at s*STG + A_SH, Bu at s*STG + A_SH + B_SH
    constexpr int STG = A_SH + 2 * B_SH;     // 13824 halves

    const int tid = threadIdx.x, lane = tid & 31, warp = tid >> 5;
    const int wm = warp >> 2, wn = warp & 3;

    // ---- load coordinates ----
    const int arow = tid >> 1, segA = (tid & 1) * 16;
    int apos = r0 + arow; if (apos > TOTAL_ROWS - 1) apos = TOTAL_ROWS - 1;
    const int ga = g_rows[apos];
    const __half* aSrc = g_x16 + (size_t)ga * H_DIM + segA;

    const int browk = tid >> 3, segB = (tid & 7) * 16;
    const __half* bgSrc = g_wg16 + (size_t)e * W_PER + (size_t)browk * F_DIM + n0 + segB;
    const __half* buSrc = g_wu16 + (size_t)e * W_PER + (size_t)browk * F_DIM + n0 + segB;

    auto load_stage = [&](int s, int k0) {
        __half* As = sm + s * STG;
        __half* Bg = As + A_SH;
        __half* Bu = Bg + B_SH;
        cp_async16(&As[arow * AST + segA],     aSrc + k0);
        cp_async16(&As[arow * AST + segA + 8], aSrc + k0 + 8);
        const size_t bo = (size_t)k0 * F_DIM;
        cp_async16(&Bg[browk * BST + segB],     bgSrc + bo);
        cp_async16(&Bg[browk * BST + segB + 8], bgSrc + bo + 8);
        cp_async16(&Bu[browk * BST + segB],     buSrc + bo);
        cp_async16(&Bu[browk * BST + segB + 8], buSrc + bo + 8);
    };

    float ag[4][4][4], au[4][4][4];
    #pragma unroll
    for (int i = 0; i < 4; i++)
        #pragma unroll
        for (int j = 0; j < 4; j++)
            #pragma unroll
            for (int k = 0; k < 4; k++) { ag[i][j][k] = 0.f; au[i][j][k] = 0.f; }

    #pragma unroll
    for (int s = 0; s < NSTAGE - 1; s++) { load_stage(s, s * BKK); cp_commit(); }

    for (int it = 0; it < KI; ++it) {
        cp_wait<NSTAGE - 2>();
        __syncthreads();
        if (it + NSTAGE - 1 < KI) load_stage((it + NSTAGE - 1) & 3, (it + NSTAGE - 1) * BKK);
        cp_commit();

        const __half* As = sm + (it & 3) * STG;
        const __half* Bg = As + A_SH;
        const __half* Bu = Bg + B_SH;
        #pragma unroll
        for (int kk = 0; kk < BKK; kk += 16) {
            uint32_t ra[4][4];
            #pragma unroll
            for (int mi = 0; mi < 4; mi++)
                ldsm_x4(ra[mi], &As[(wm*64 + mi*16 + (lane & 15)) * AST
                                     + kk + (lane >> 4) * 8]);
            uint32_t rbg[2][4], rbu[2][4];
            const int mat = lane >> 3, rr2 = lane & 7;
            #pragma unroll
            for (int bj = 0; bj < 2; bj++) {
                const int boff = (kk + (mat & 1) * 8 + rr2) * BST
                                 + wn*32 + bj*16 + (mat >> 1) * 8;
                ldsm_x4_t(rbg[bj], Bg + boff);
                ldsm_x4_t(rbu[bj], Bu + boff);
            }
            #pragma unroll
            for (int mi = 0; mi < 4; mi++)
                #pragma unroll
                for (int nj = 0; nj < 4; nj++) {
                    mma_16816(ag[mi][nj], ra[mi],
                              rbg[nj >> 1][(nj & 1) * 2], rbg[nj >> 1][(nj & 1) * 2 + 1]);
                    mma_16816(au[mi][nj], ra[mi],
                              rbu[nj >> 1][(nj & 1) * 2], rbu[nj >> 1][(nj & 1) * 2 + 1]);
                }
        }
        __syncthreads();
    }

    // ---- SwiGLU epilogue straight from fp32 accumulators ----
    #pragma unroll
    for (int mi = 0; mi < 4; mi++) {
        #pragma unroll
        for (int nj = 0; nj < 4; nj++) {
            const int rr = wm*64 + mi*16 + (lane >> 2);
            const int cc = n0 + wn*32 + nj*8 + (lane & 3) * 2;
            float* g = ag[mi][nj];
            float* u = au[mi][nj];
            if (rr < rows) {
                float h0 = g[0] * u[0] / (1.f + expf(-g[0]));
                float h1 = g[1] * u[1] / (1.f + expf(-g[1]));
                *(__half2*)&g_hbuf[(size_t)(r0 + rr) * F_DIM + cc] =
                    __floats2half2_rn(h0, h1);
            }
            if (rr + 8 < rows) {
                float h2 = g[2] * u[2] / (1.f + expf(-g[2]));
                float h3 = g[3] * u[3] / (1.f + expf(-g[3]));
                *(__half2*)&g_hbuf[(size_t)(r0 + rr + 8) * F_DIM + cc] =
                    __floats2half2_rn(h2, h3);
            }
        }
    }
}

// ---------------- down GEMM (K=2816) + weighted atomic scatter ---------------
__global__ void __launch_bounds__(256, 2) down_kernel(float* __restrict__ out) {
    const int mt = blockIdx.y;
    if (mt >= g_tile_count) return;
    const int e    = g_tile_e[mt];
    const int r0   = g_tile_r0[mt];
    const int rows = g_tile_rows[mt];
    const int n0   = blockIdx.x * BN;
    constexpr int KI = F_DIM / BKK;          // 88

    extern __shared__ __half sm[];
    constexpr int STG = A_SH + B_SH;         // 9472 halves

    const int tid = threadIdx.x, lane = tid & 31, warp = tid >> 5;
    const int wm = warp >> 2, wn = warp & 3;

    const int arow = tid >> 1, segA = (tid & 1) * 16;
    int apos = r0 + arow; if (apos > TOTAL_ROWS - 1) apos = TOTAL_ROWS - 1;
    const __half* aSrc = g_hbuf + (size_t)apos * F_DIM + segA;

    const int browk = tid >> 3, segB = (tid & 7) * 16;
    const __half* bSrc = g_wd16 + (size_t)e * W_PER + (size_t)browk * H_DIM + n0 + segB;

    auto load_stage = [&](int s, int k0) {
        __half* As = sm + s * STG;
        __half* Bs = As + A_SH;
        cp_async16(&As[arow * AST + segA],     aSrc + k0);
        cp_async16(&As[arow * AST + segA + 8], aSrc + k0 + 8);
        const size_t bo = (size_t)k0 * H_DIM;
        cp_async16(&Bs[browk * BST + segB],     bSrc + bo);
        cp_async16(&Bs[browk * BST + segB + 8], bSrc + bo + 8);
    };

    float acc[4][4][4];
    #pragma unroll
    for (int i = 0; i < 4; i++)
        #pragma unroll
        for (int j = 0; j < 4; j++)
            #pragma unroll
            for (int k = 0; k < 4; k++) acc[i][j][k] = 0.f;

    #pragma unroll
    for (int s = 0; s < NSTAGE - 1; s++) { load_stage(s, s * BKK); cp_commit(); }

    for (int it = 0; it < KI; ++it) {
        cp_wait<NSTAGE - 2>();
        __syncthreads();
        if (it + NSTAGE - 1 < KI) load_stage((it + NSTAGE - 1) & 3, (it + NSTAGE - 1) * BKK);
        cp_commit();

        const __half* As = sm + (it & 3) * STG;
        const __half* Bs = As + A_SH;
        #pragma unroll
        for (int kk = 0; kk < BKK; kk += 16) {
            uint32_t ra[4][4];
            #pragma unroll
            for (int mi = 0; mi < 4; mi++)
                ldsm_x4(ra[mi], &As[(wm*64 + mi*16 + (lane & 15)) * AST
                                     + kk + (lane >> 4) * 8]);
            uint32_t rb[2][4];
            const int mat = lane >> 3, rr2 = lane & 7;
            #pragma unroll
            for (int bj = 0; bj < 2; bj++)
                ldsm_x4_t(rb[bj], &Bs[(kk + (mat & 1) * 8 + rr2) * BST
                                       + wn*32 + bj*16 + (mat >> 1) * 8]);
            #pragma unroll
            for (int mi = 0; mi < 4; mi++)
                #pragma unroll
                for (int nj = 0; nj < 4; nj++)
                    mma_16816(acc[mi][nj], ra[mi],
                              rb[nj >> 1][(nj & 1) * 2], rb[nj >> 1][(nj & 1) * 2 + 1]);
        }
        __syncthreads();
    }

    #pragma unroll
    for (int mi = 0; mi < 4; mi++) {
        #pragma unroll
        for (int nj = 0; nj < 4; nj++) {
            const int rr = wm*64 + mi*16 + (lane >> 2);
            const int cc = n0 + wn*32 + nj*8 + (lane & 3) * 2;
            float* a = acc[mi][nj];
            if (rr < rows) {
                int tok = g_rows[r0 + rr]; float w = g_wv[r0 + rr];
                atomicAdd(&out[(size_t)tok * H_DIM + cc],     w * a[0]);
                atomicAdd(&out[(size_t)tok * H_DIM + cc + 1], w * a[1]);
            }
            if (rr + 8 < rows) {
                int tok = g_rows[r0 + rr + 8]; float w = g_wv[r0 + rr + 8];
                atomicAdd(&out[(size_t)tok * H_DIM + cc],     w * a[2]);
                atomicAdd(&out[(size_t)tok * H_DIM + cc + 1], w * a[3]);
            }
        }
    }
}

// ---------------- launch ------------------------------------------------------
extern "C" void kernel_launch(void* const* d_in, const int* in_sizes, int n_in,
                              void* d_out, int out_size) {
    const float* hs  = (const float*)d_in[0];
    const float* lnw = (const float*)d_in[1];
    const float* rw  = (const float*)d_in[2];
    const float* wg  = (const float*)d_in[3];
    const float* wu  = (const float*)d_in[4];
    const float* wd  = (const float*)d_in[5];
    float* out = (float*)d_out;

    constexpr int SM_GU = NSTAGE * (A_SH + 2 * B_SH) * 2;   // 110592 B
    constexpr int SM_DN = NSTAGE * (A_SH + B_SH) * 2;       // 75776 B
    cudaFuncSetAttribute(gateup_kernel,
                         cudaFuncAttributeMaxDynamicSharedMemorySize, SM_GU);
    cudaFuncSetAttribute(down_kernel,
                         cudaFuncAttributeMaxDynamicSharedMemorySize, SM_DN);

    init_kernel<<<1, 32>>>();
    convert_kernel<<<1184, 256>>>((const float4*)wg, (const float4*)wu,
                                  (const float4*)wd);
    rmsnorm_router_kernel<<<T_TOK, 256>>>(hs, lnw, rw);
    build_tiles_kernel<<<1, 1>>>();
    scatter_kernel<<<32, 256>>>();
    zero_out_kernel<<<512, 256>>>((float4*)d_out);

    gateup_kernel<<<dim3(F_DIM / BN, 72), 256, SM_GU>>>();
    down_kernel<<<dim3(H_DIM / BN, 72), 256, SM_DN>>>(out);
}

// round 6
// speedup vs baseline: 1.0031x; 1.0031x over previous
#include <cuda_runtime.h>
#include <cuda_fp16.h>
#include <cstdint>

#define T_TOK 4096
#define H_DIM 1024
#define F_DIM 2816
#define N_EXP 8
#define TOTAL_ROWS (2*T_TOK)
#define W_PER ((size_t)H_DIM * F_DIM)
#define W_ELEMS (8ull*1024ull*2816ull)

#define BM 128
#define BN 128
#define BKK 32
#define AST 40      // A smem row stride (halves)
#define BST 136     // B smem row stride (halves)
#define NSTAGE 4
#define A_SH (BM * AST)                 // 5120 halves
#define B_SH (BKK * BST)                // 4352 halves

// ---------------- device scratch ---------------------------------------------
__device__ __half g_wg16[W_ELEMS];      // [E][H][F]
__device__ __half g_wu16[W_ELEMS];      // [E][H][F]
__device__ __half g_wd16[W_ELEMS];      // [E][F][H]
__device__ __half g_x16[(size_t)T_TOK * H_DIM];
__device__ __half g_hbuf[(size_t)TOTAL_ROWS * F_DIM];
__device__ int    g_counts[N_EXP];
__device__ int    g_cursor[N_EXP];
__device__ int    g_offs[N_EXP];
__device__ int    g_eid[TOTAL_ROWS];
__device__ float  g_ewt[TOTAL_ROWS];
__device__ int    g_rows[TOTAL_ROWS];
__device__ float  g_wv[TOTAL_ROWS];
__device__ int    g_tile_e[80];
__device__ int    g_tile_r0[80];
__device__ int    g_tile_rows[80];
__device__ int    g_tile_count;

// ---------------- PTX helpers -------------------------------------------------
__device__ __forceinline__ unsigned smem_u32(const void* p) {
    return (unsigned)__cvta_generic_to_shared(p);
}
__device__ __forceinline__ void cp_async16(const void* smem, const void* g) {
    asm volatile("cp.async.cg.shared.global [%0], [%1], 16;"
                 :: "r"(smem_u32(smem)), "l"(g));
}
__device__ __forceinline__ void cp_commit() {
    asm volatile("cp.async.commit_group;" ::: "memory");
}
template <int N>
__device__ __forceinline__ void cp_wait() {
    asm volatile("cp.async.wait_group %0;" :: "n"(N) : "memory");
}
__device__ __forceinline__ void ldsm_x4(uint32_t r[4], const __half* p) {
    asm volatile("ldmatrix.sync.aligned.m8n8.x4.shared.b16 {%0,%1,%2,%3}, [%4];"
                 : "=r"(r[0]), "=r"(r[1]), "=r"(r[2]), "=r"(r[3])
                 : "r"(smem_u32(p)));
}
__device__ __forceinline__ void ldsm_x4_t(uint32_t r[4], const __half* p) {
    asm volatile("ldmatrix.sync.aligned.m8n8.x4.trans.shared.b16 {%0,%1,%2,%3}, [%4];"
                 : "=r"(r[0]), "=r"(r[1]), "=r"(r[2]), "=r"(r[3])
                 : "r"(smem_u32(p)));
}
__device__ __forceinline__ void mma_16816(float* c, const uint32_t* a,
                                          uint32_t b0, uint32_t b1) {
    asm volatile(
        "mma.sync.aligned.m16n8k16.row.col.f32.f16.f16.f32 "
        "{%0,%1,%2,%3},{%4,%5,%6,%7},{%8,%9},{%0,%1,%2,%3};"
        : "+f"(c[0]), "+f"(c[1]), "+f"(c[2]), "+f"(c[3])
        : "r"(a[0]), "r"(a[1]), "r"(a[2]), "r"(a[3]), "r"(b0), "r"(b1));
}

// ---------------- tiny kernels ----------------------------------------------
__global__ void init_kernel() {
    int i = threadIdx.x;
    if (i < N_EXP) { g_counts[i] = 0; g_cursor[i] = 0; }
}

__global__ void zero_out_kernel(float4* out) {
    size_t n = (size_t)T_TOK * H_DIM / 4;
    for (size_t i = blockIdx.x * (size_t)blockDim.x + threadIdx.x; i < n;
         i += (size_t)gridDim.x * blockDim.x)
        out[i] = make_float4(0.f, 0.f, 0.f, 0.f);
}

__global__ void convert_kernel(const float4* __restrict__ wg,
                               const float4* __restrict__ wu,
                               const float4* __restrict__ wd) {
    size_t n = W_ELEMS / 4;
    __half2* og = (__half2*)g_wg16;
    __half2* ou = (__half2*)g_wu16;
    __half2* od = (__half2*)g_wd16;
    for (size_t i = blockIdx.x * (size_t)blockDim.x + threadIdx.x; i < n;
         i += (size_t)gridDim.x * blockDim.x) {
        float4 a = wg[i];
        og[2*i]   = __floats2half2_rn(a.x, a.y);
        og[2*i+1] = __floats2half2_rn(a.z, a.w);
        float4 b = wu[i];
        ou[2*i]   = __floats2half2_rn(b.x, b.y);
        ou[2*i+1] = __floats2half2_rn(b.z, b.w);
        float4 c = wd[i];
        od[2*i]   = __floats2half2_rn(c.x, c.y);
        od[2*i+1] = __floats2half2_rn(c.z, c.w);
    }
}

// ---------------- RMSNorm + router + top2 ------------------------------------
__global__ void rmsnorm_router_kernel(const float* __restrict__ hs,
                                      const float* __restrict__ lnw,
                                      const float* __restrict__ rw) {
    const int t = blockIdx.x;
    const int tid = threadIdx.x, lane = tid & 31, warp = tid >> 5;

    float4 xv = *(const float4*)(hs + (size_t)t * H_DIM + tid * 4);
    float ss = xv.x*xv.x + xv.y*xv.y + xv.z*xv.z + xv.w*xv.w;
    #pragma unroll
    for (int o = 16; o; o >>= 1) ss += __shfl_xor_sync(0xffffffffu, ss, o);

    __shared__ float sred[8];
    __shared__ float sinv;
    if (lane == 0) sred[warp] = ss;
    __syncthreads();
    if (tid == 0) {
        float v = 0.f;
        #pragma unroll
        for (int w = 0; w < 8; w++) v += sred[w];
        sinv = rsqrtf(v * (1.0f / H_DIM) + 1e-5f);
    }
    __syncthreads();
    float inv = sinv;

    float4 lw = *(const float4*)(lnw + tid * 4);
    float xn[4] = {xv.x*inv*lw.x, xv.y*inv*lw.y, xv.z*inv*lw.z, xv.w*inv*lw.w};

    __half2* xd = (__half2*)(g_x16 + (size_t)t * H_DIM + tid * 4);
    xd[0] = __floats2half2_rn(xn[0], xn[1]);
    xd[1] = __floats2half2_rn(xn[2], xn[3]);

    float lp[8] = {0,0,0,0,0,0,0,0};
    #pragma unroll
    for (int r = 0; r < 4; r++) {
        const float4 w0 = *(const float4*)(rw + (size_t)(tid*4 + r) * N_EXP);
        const float4 w1 = *(const float4*)(rw + (size_t)(tid*4 + r) * N_EXP + 4);
        float xr = xn[r];
        lp[0] += xr*w0.x; lp[1] += xr*w0.y; lp[2] += xr*w0.z; lp[3] += xr*w0.w;
        lp[4] += xr*w1.x; lp[5] += xr*w1.y; lp[6] += xr*w1.z; lp[7] += xr*w1.w;
    }
    #pragma unroll
    for (int e = 0; e < 8; e++)
        #pragma unroll
        for (int o = 16; o; o >>= 1) lp[e] += __shfl_xor_sync(0xffffffffu, lp[e], o);

    __shared__ float sl[8][8];
    if (lane == 0) {
        #pragma unroll
        for (int e = 0; e < 8; e++) sl[warp][e] = lp[e];
    }
    __syncthreads();
    if (tid == 0) {
        float l[8], m = -1e30f;
        #pragma unroll
        for (int e = 0; e < 8; e++) {
            float v = 0.f;
            #pragma unroll
            for (int w = 0; w < 8; w++) v += sl[w][e];
            l[e] = v; m = fmaxf(m, v);
        }
        float p[8], s = 0.f;
        #pragma unroll
        for (int e = 0; e < 8; e++) { p[e] = expf(l[e] - m); s += p[e]; }
        float is = 1.f / s;
        int b1 = 0; float v1 = -1.f;
        #pragma unroll
        for (int e = 0; e < 8; e++) if (p[e] > v1) { v1 = p[e]; b1 = e; }
        int b2 = 0; float v2 = -1.f;
        #pragma unroll
        for (int e = 0; e < 8; e++) if (e != b1 && p[e] > v2) { v2 = p[e]; b2 = e; }
        g_eid[2*t]   = b1; g_ewt[2*t]   = v1 * is;
        g_eid[2*t+1] = b2; g_ewt[2*t+1] = v2 * is;
        atomicAdd(&g_counts[b1], 1);
        atomicAdd(&g_counts[b2], 1);
    }
}

__global__ void build_tiles_kernel() {
    int off = 0;
    for (int e = 0; e < N_EXP; e++) { g_offs[e] = off; off += g_counts[e]; }
    int tc = 0;
    for (int e = 0; e < N_EXP; e++) {
        int beg = g_offs[e], end = beg + g_counts[e];
        for (int r = beg; r < end; r += 128) {
            g_tile_e[tc] = e; g_tile_r0[tc] = r;
            g_tile_rows[tc] = min(128, end - r);
            tc++;
        }
    }
    g_tile_count = tc;
}

__global__ void scatter_kernel() {
    int i = blockIdx.x * blockDim.x + threadIdx.x;
    if (i < TOTAL_ROWS) {
        int e = g_eid[i];
        int pos = g_offs[e] + atomicAdd(&g_cursor[e], 1);
        g_rows[pos] = i >> 1;
        g_wv[pos] = g_ewt[i];
    }
}

// ---------------- fused gate+up+SwiGLU GEMM ----------------------------------
// C = [gate | up] for one 128-row tile x 128 F-cols; epilogue writes hbuf fp16.
__global__ void __launch_bounds__(256, 1) gateup_kernel() {
    const int mt = blockIdx.y;
    if (mt >= g_tile_count) return;
    const int e    = g_tile_e[mt];
    const int r0   = g_tile_r0[mt];
    const int rows = g_tile_rows[mt];
    const int n0   = blockIdx.x * BN;
    constexpr int KI = H_DIM / BKK;          // 32

    extern __shared__ __half sm[];
    // stage s: A at s*STG, Bg at s*STG + A_SH, Bu at s*STG + A_SH + B_SH
    constexpr int STG = A_SH + 2 * B_SH;     // 13824 halves

    const int tid = threadIdx.x, lane = tid & 31, warp = tid >> 5;
    const int wm = warp >> 2, wn = warp & 3;

    // ---- load coordinates ----
    const int arow = tid >> 1, segA = (tid & 1) * 16;
    int apos = r0 + arow; if (apos > TOTAL_ROWS - 1) apos = TOTAL_ROWS - 1;
    const int ga = g_rows[apos];
    const __half* aSrc = g_x16 + (size_t)ga * H_DIM + segA;

    const int browk = tid >> 3, segB = (tid & 7) * 16;
    const __half* bgSrc = g_wg16 + (size_t)e * W_PER + (size_t)browk * F_DIM + n0 + segB;
    const __half* buSrc = g_wu16 + (size_t)e * W_PER + (size_t)browk * F_DIM + n0 + segB;

    auto load_stage = [&](int s, int k0) {
        __half* As = sm + s * STG;
        __half* Bg = As + A_SH;
        __half* Bu = Bg + B_SH;
        cp_async16(&As[arow * AST + segA],     aSrc + k0);
        cp_async16(&As[arow * AST + segA + 8], aSrc + k0 + 8);
        const size_t bo = (size_t)k0 * F_DIM;
        cp_async16(&Bg[browk * BST + segB],     bgSrc + bo);
        cp_async16(&Bg[browk * BST + segB + 8], bgSrc + bo + 8);
        cp_async16(&Bu[browk * BST + segB],     buSrc + bo);
        cp_async16(&Bu[browk * BST + segB + 8], buSrc + bo + 8);
    };

    float ag[4][4][4], au[4][4][4];
    #pragma unroll
    for (int i = 0; i < 4; i++)
        #pragma unroll
        for (int j = 0; j < 4; j++)
            #pragma unroll
            for (int k = 0; k < 4; k++) { ag[i][j][k] = 0.f; au[i][j][k] = 0.f; }

    #pragma unroll
    for (int s = 0; s < NSTAGE - 1; s++) { load_stage(s, s * BKK); cp_commit(); }

    for (int it = 0; it < KI; ++it) {
        cp_wait<NSTAGE - 2>();
        __syncthreads();
        if (it + NSTAGE - 1 < KI) load_stage((it + NSTAGE - 1) & 3, (it + NSTAGE - 1) * BKK);
        cp_commit();

        const __half* As = sm + (it & 3) * STG;
        const __half* Bg = As + A_SH;
        const __half* Bu = Bg + B_SH;
        #pragma unroll
        for (int kk = 0; kk < BKK; kk += 16) {
            uint32_t ra[4][4];
            #pragma unroll
            for (int mi = 0; mi < 4; mi++)
                ldsm_x4(ra[mi], &As[(wm*64 + mi*16 + (lane & 15)) * AST
                                     + kk + (lane >> 4) * 8]);
            uint32_t rbg[2][4], rbu[2][4];
            const int mat = lane >> 3, rr2 = lane & 7;
            #pragma unroll
            for (int bj = 0; bj < 2; bj++) {
                const int boff = (kk + (mat & 1) * 8 + rr2) * BST
                                 + wn*32 + bj*16 + (mat >> 1) * 8;
                ldsm_x4_t(rbg[bj], Bg + boff);
                ldsm_x4_t(rbu[bj], Bu + boff);
            }
            #pragma unroll
            for (int mi = 0; mi < 4; mi++)
                #pragma unroll
                for (int nj = 0; nj < 4; nj++) {
                    mma_16816(ag[mi][nj], ra[mi],
                              rbg[nj >> 1][(nj & 1) * 2], rbg[nj >> 1][(nj & 1) * 2 + 1]);
                    mma_16816(au[mi][nj], ra[mi],
                              rbu[nj >> 1][(nj & 1) * 2], rbu[nj >> 1][(nj & 1) * 2 + 1]);
                }
        }
        __syncthreads();
    }

    // ---- SwiGLU epilogue straight from fp32 accumulators ----
    #pragma unroll
    for (int mi = 0; mi < 4; mi++) {
        #pragma unroll
        for (int nj = 0; nj < 4; nj++) {
            const int rr = wm*64 + mi*16 + (lane >> 2);
            const int cc = n0 + wn*32 + nj*8 + (lane & 3) * 2;
            float* g = ag[mi][nj];
            float* u = au[mi][nj];
            if (rr < rows) {
                float h0 = g[0] * u[0] / (1.f + expf(-g[0]));
                float h1 = g[1] * u[1] / (1.f + expf(-g[1]));
                *(__half2*)&g_hbuf[(size_t)(r0 + rr) * F_DIM + cc] =
                    __floats2half2_rn(h0, h1);
            }
            if (rr + 8 < rows) {
                float h2 = g[2] * u[2] / (1.f + expf(-g[2]));
                float h3 = g[3] * u[3] / (1.f + expf(-g[3]));
                *(__half2*)&g_hbuf[(size_t)(r0 + rr + 8) * F_DIM + cc] =
                    __floats2half2_rn(h2, h3);
            }
        }
    }
}

// ---------------- down GEMM (K=2816) + weighted atomic scatter ---------------
__global__ void __launch_bounds__(256, 2) down_kernel(float* __restrict__ out) {
    const int mt = blockIdx.y;
    if (mt >= g_tile_count) return;
    const int e    = g_tile_e[mt];
    const int r0   = g_tile_r0[mt];
    const int rows = g_tile_rows[mt];
    const int n0   = blockIdx.x * BN;
    constexpr int KI = F_DIM / BKK;          // 88

    extern __shared__ __half sm[];
    constexpr int STG = A_SH + B_SH;         // 9472 halves

    const int tid = threadIdx.x, lane = tid & 31, warp = tid >> 5;
    const int wm = warp >> 2, wn = warp & 3;

    const int arow = tid >> 1, segA = (tid & 1) * 16;
    int apos = r0 + arow; if (apos > TOTAL_ROWS - 1) apos = TOTAL_ROWS - 1;
    const __half* aSrc = g_hbuf + (size_t)apos * F_DIM + segA;

    const int browk = tid >> 3, segB = (tid & 7) * 16;
    const __half* bSrc = g_wd16 + (size_t)e * W_PER + (size_t)browk * H_DIM + n0 + segB;

    auto load_stage = [&](int s, int k0) {
        __half* As = sm + s * STG;
        __half* Bs = As + A_SH;
        cp_async16(&As[arow * AST + segA],     aSrc + k0);
        cp_async16(&As[arow * AST + segA + 8], aSrc + k0 + 8);
        const size_t bo = (size_t)k0 * H_DIM;
        cp_async16(&Bs[browk * BST + segB],     bSrc + bo);
        cp_async16(&Bs[browk * BST + segB + 8], bSrc + bo + 8);
    };

    float acc[4][4][4];
    #pragma unroll
    for (int i = 0; i < 4; i++)
        #pragma unroll
        for (int j = 0; j < 4; j++)
            #pragma unroll
            for (int k = 0; k < 4; k++) acc[i][j][k] = 0.f;

    #pragma unroll
    for (int s = 0; s < NSTAGE - 1; s++) { load_stage(s, s * BKK); cp_commit(); }

    for (int it = 0; it < KI; ++it) {
        cp_wait<NSTAGE - 2>();
        __syncthreads();
        if (it + NSTAGE - 1 < KI) load_stage((it + NSTAGE - 1) & 3, (it + NSTAGE - 1) * BKK);
        cp_commit();

        const __half* As = sm + (it & 3) * STG;
        const __half* Bs = As + A_SH;
        #pragma unroll
        for (int kk = 0; kk < BKK; kk += 16) {
            uint32_t ra[4][4];
            #pragma unroll
            for (int mi = 0; mi < 4; mi++)
                ldsm_x4(ra[mi], &As[(wm*64 + mi*16 + (lane & 15)) * AST
                                     + kk + (lane >> 4) * 8]);
            uint32_t rb[2][4];
            const int mat = lane >> 3, rr2 = lane & 7;
            #pragma unroll
            for (int bj = 0; bj < 2; bj++)
                ldsm_x4_t(rb[bj], &Bs[(kk + (mat & 1) * 8 + rr2) * BST
                                       + wn*32 + bj*16 + (mat >> 1) * 8]);
            #pragma unroll
            for (int mi = 0; mi < 4; mi++)
                #pragma unroll
                for (int nj = 0; nj < 4; nj++)
                    mma_16816(acc[mi][nj], ra[mi],
                              rb[nj >> 1][(nj & 1) * 2], rb[nj >> 1][(nj & 1) * 2 + 1]);
        }
        __syncthreads();
    }

    #pragma unroll
    for (int mi = 0; mi < 4; mi++) {
        #pragma unroll
        for (int nj = 0; nj < 4; nj++) {
            const int rr = wm*64 + mi*16 + (lane >> 2);
            const int cc = n0 + wn*32 + nj*8 + (lane & 3) * 2;
            float* a = acc[mi][nj];
            if (rr < rows) {
                int tok = g_rows[r0 + rr]; float w = g_wv[r0 + rr];
                atomicAdd(&out[(size_t)tok * H_DIM + cc],     w * a[0]);
                atomicAdd(&out[(size_t)tok * H_DIM + cc + 1], w * a[1]);
            }
            if (rr + 8 < rows) {
                int tok = g_rows[r0 + rr + 8]; float w = g_wv[r0 + rr + 8];
                atomicAdd(&out[(size_t)tok * H_DIM + cc],     w * a[2]);
                atomicAdd(&out[(size_t)tok * H_DIM + cc + 1], w * a[3]);
            }
        }
    }
}

// ---------------- launch ------------------------------------------------------
extern "C" void kernel_launch(void* const* d_in, const int* in_sizes, int n_in,
                              void* d_out, int out_size) {
    const float* hs  = (const float*)d_in[0];
    const float* lnw = (const float*)d_in[1];
    const float* rw  = (const float*)d_in[2];
    const float* wg  = (const float*)d_in[3];
    const float* wu  = (const float*)d_in[4];
    const float* wd  = (const float*)d_in[5];
    float* out = (float*)d_out;

    constexpr int SM_GU = NSTAGE * (A_SH + 2 * B_SH) * 2;   // 110592 B
    constexpr int SM_DN = NSTAGE * (A_SH + B_SH) * 2;       // 75776 B
    cudaFuncSetAttribute(gateup_kernel,
                         cudaFuncAttributeMaxDynamicSharedMemorySize, SM_GU);
    cudaFuncSetAttribute(down_kernel,
                         cudaFuncAttributeMaxDynamicSharedMemorySize, SM_DN);

    init_kernel<<<1, 32>>>();
    convert_kernel<<<1184, 256>>>((const float4*)wg, (const float4*)wu,
                                  (const float4*)wd);
    rmsnorm_router_kernel<<<T_TOK, 256>>>(hs, lnw, rw);
    build_tiles_kernel<<<1, 1>>>();
    scatter_kernel<<<32, 256>>>();
    zero_out_kernel<<<512, 256>>>((float4*)d_out);

    gateup_kernel<<<dim3(F_DIM / BN, 72), 256, SM_GU>>>();
    down_kernel<<<dim3(H_DIM / BN, 72), 256, SM_DN>>>(out);
}